// round 1
// baseline (speedup 1.0000x reference)
#include <cuda_runtime.h>

#define N_HOSTN 50000
#define N_FLOWN 200000
#define NEDGE   1000000
#define DIM     128
#define D_OUT   32

// ---------------- device scratch (static: no allocations allowed) ----------
__device__ int   g_deg[N_FLOWN + 1];
__device__ int   g_rowptr_f[N_FLOWN + 1];
__device__ int   g_rowptr_h[N_HOSTN + 1];
__device__ int   g_col_f[NEDGE];
__device__ int   g_col_h[NEDGE];
__device__ int   g_partials[256];
__device__ float g_mean[(size_t)N_FLOWN * DIM];
__device__ float g_fa[(size_t)N_FLOWN * DIM];
__device__ float g_fb[(size_t)N_FLOWN * DIM];
__device__ float g_ha[(size_t)N_HOSTN * DIM];
__device__ float g_hb[(size_t)N_HOSTN * DIM];

// ---------------- small utility kernels ------------------------------------
__global__ void zero_kernel(int* p, int n) {
    int i = blockIdx.x * blockDim.x + threadIdx.x;
    if (i < n) p[i] = 0;
}

__global__ void hist_kernel(const int* __restrict__ dst, int* __restrict__ deg, int n) {
    for (int i = blockIdx.x * blockDim.x + threadIdx.x; i < n; i += gridDim.x * blockDim.x)
        atomicAdd(&deg[dst[i]], 1);
}

// ---- 3-phase exclusive scan over n ints (chunk = 1024 per block) ----------
__global__ void scan_blocks(const int* __restrict__ in, int* __restrict__ out,
                            int* __restrict__ partials, int n) {
    __shared__ int sh[256];
    int t = threadIdx.x;
    int base = blockIdx.x * 1024 + t * 4;
    int v0 = (base + 0 < n) ? in[base + 0] : 0;
    int v1 = (base + 1 < n) ? in[base + 1] : 0;
    int v2 = (base + 2 < n) ? in[base + 2] : 0;
    int v3 = (base + 3 < n) ? in[base + 3] : 0;
    int s = v0 + v1 + v2 + v3;
    sh[t] = s;
    __syncthreads();
    for (int off = 1; off < 256; off <<= 1) {
        int y = (t >= off) ? sh[t - off] : 0;
        __syncthreads();
        sh[t] += y;
        __syncthreads();
    }
    int excl = sh[t] - s;
    if (t == 255) partials[blockIdx.x] = sh[255];
    int run = excl;
    if (base + 0 < n) out[base + 0] = run; run += v0;
    if (base + 1 < n) out[base + 1] = run; run += v1;
    if (base + 2 < n) out[base + 2] = run; run += v2;
    if (base + 3 < n) out[base + 3] = run;
}

__global__ void scan_partials(int* partials, int nb) {
    __shared__ int sh[256];
    int t = threadIdx.x;
    int v = (t < nb) ? partials[t] : 0;
    sh[t] = v;
    __syncthreads();
    for (int off = 1; off < 256; off <<= 1) {
        int y = (t >= off) ? sh[t - off] : 0;
        __syncthreads();
        sh[t] += y;
        __syncthreads();
    }
    if (t < nb) partials[t] = sh[t] - v;  // exclusive
}

__global__ void scan_add(int* __restrict__ out, const int* __restrict__ partials, int n) {
    for (int i = blockIdx.x * blockDim.x + threadIdx.x; i < n; i += gridDim.x * blockDim.x)
        out[i] += partials[i >> 10];
}

__global__ void fill_kernel(const int* __restrict__ src, const int* __restrict__ dst,
                            const int* __restrict__ rowptr, int* __restrict__ cursor,
                            int* __restrict__ col, int n) {
    for (int e = blockIdx.x * blockDim.x + threadIdx.x; e < n; e += gridDim.x * blockDim.x) {
        int d = dst[e];
        int p = rowptr[d] + atomicAdd(&cursor[d], 1);
        col[p] = src[e];
    }
}

// ---------------- mean aggregation (pull via CSR) ---------------------------
// one warp per destination node; each lane owns a float4 (32*4 = 128 feats)
__global__ void aggregate_kernel(const float* __restrict__ xsrc,
                                 const int* __restrict__ rowptr,
                                 const int* __restrict__ col,
                                 float* __restrict__ outmean, int ndst) {
    int warp = (blockIdx.x * blockDim.x + threadIdx.x) >> 5;
    int lane = threadIdx.x & 31;
    if (warp >= ndst) return;
    int start = rowptr[warp];
    int end   = rowptr[warp + 1];
    const float4* base = (const float4*)xsrc;
    float4 acc = make_float4(0.f, 0.f, 0.f, 0.f);
#pragma unroll 2
    for (int e = start; e < end; e++) {
        int s = __ldg(&col[e]);
        float4 v = __ldg(&base[(size_t)s * 32 + lane]);
        acc.x += v.x; acc.y += v.y; acc.z += v.z; acc.w += v.w;
    }
    int deg = end - start;
    float inv = 1.f / (float)(deg > 1 ? deg : 1);
    acc.x *= inv; acc.y *= inv; acc.z *= inv; acc.w *= inv;
    ((float4*)outmean)[(size_t)warp * 32 + lane] = acc;
}

// ---------------- fused GEMM: C = act([A0|A1] @ [B0;B1] + bias0 + bias1) ----
// A sources are row-major [M,128]; B sources row-major [128,BN]; C [M,BN].
template <int BM, int BN, int BK, bool DUAL, bool ACT>
__global__ __launch_bounds__(256) void gemm_kernel(
    const float* __restrict__ A0, const float* __restrict__ A1,
    const float* __restrict__ B0, const float* __restrict__ B1,
    const float* __restrict__ bias0, const float* __restrict__ bias1,
    float* __restrict__ C, int M)
{
    constexpr int KTOT  = DUAL ? 2 * DIM : DIM;
    constexpr int BMP   = BM + 1;            // pad to kill STS bank conflicts
    constexpr int TCOLS = BN / 4;
    constexpr int TROWS = 256 / TCOLS;
    constexpr int TM    = BM / TROWS;

    __shared__ float As[BK * BMP];
    __shared__ float Bs[BK * BN];

    int tid = threadIdx.x;
    int tcol = tid % TCOLS;
    int trow = tid / TCOLS;
    int rowbase = blockIdx.x * BM;
    int colbase = tcol * 4;

    float acc[TM][4];
#pragma unroll
    for (int i = 0; i < TM; i++)
#pragma unroll
        for (int j = 0; j < 4; j++) acc[i][j] = 0.f;

    for (int k0 = 0; k0 < KTOT; k0 += BK) {
        // A tile -> As (transposed: As[k][row])
#pragma unroll
        for (int idx = tid; idx < BM * BK; idx += 256) {
            int r  = idx / BK;
            int kk = idx % BK;
            int row = rowbase + r;
            float v = 0.f;
            if (row < M) {
                const float* A = A0;
                int ko = k0 + kk;
                if (DUAL && ko >= DIM) { A = A1; ko -= DIM; }
                v = __ldg(A + (size_t)row * DIM + ko);
            }
            As[kk * BMP + r] = v;
        }
        // B tile -> Bs[k][n]
#pragma unroll
        for (int idx = tid; idx < BK * BN; idx += 256) {
            int kk = idx / BN;
            int n  = idx % BN;
            const float* B = B0;
            int ko = k0 + kk;
            if (DUAL && ko >= DIM) { B = B1; ko -= DIM; }
            Bs[kk * BN + n] = __ldg(B + (size_t)ko * BN + n);
        }
        __syncthreads();

#pragma unroll
        for (int kk = 0; kk < BK; kk++) {
            float4 b = *(const float4*)&Bs[kk * BN + colbase];
            float a[TM];
#pragma unroll
            for (int i = 0; i < TM; i++) a[i] = As[kk * BMP + trow * TM + i];
#pragma unroll
            for (int i = 0; i < TM; i++) {
                acc[i][0] += a[i] * b.x;
                acc[i][1] += a[i] * b.y;
                acc[i][2] += a[i] * b.z;
                acc[i][3] += a[i] * b.w;
            }
        }
        __syncthreads();
    }

    // epilogue: bias (+second bias), optional leaky relu, store
    float4 bb;
    bb.x = bias0[colbase + 0] + (DUAL ? bias1[colbase + 0] : 0.f);
    bb.y = bias0[colbase + 1] + (DUAL ? bias1[colbase + 1] : 0.f);
    bb.z = bias0[colbase + 2] + (DUAL ? bias1[colbase + 2] : 0.f);
    bb.w = bias0[colbase + 3] + (DUAL ? bias1[colbase + 3] : 0.f);

#pragma unroll
    for (int i = 0; i < TM; i++) {
        int row = rowbase + trow * TM + i;
        if (row < M) {
            float4 v;
            v.x = acc[i][0] + bb.x;
            v.y = acc[i][1] + bb.y;
            v.z = acc[i][2] + bb.z;
            v.w = acc[i][3] + bb.w;
            if (ACT) {
                v.x = v.x > 0.f ? v.x : 0.01f * v.x;
                v.y = v.y > 0.f ? v.y : 0.01f * v.y;
                v.z = v.z > 0.f ? v.z : 0.01f * v.z;
                v.w = v.w > 0.f ? v.w : 0.01f * v.w;
            }
            *(float4*)&C[(size_t)row * BN + colbase] = v;
        }
    }
}

// ---------------- host side -------------------------------------------------
static void build_csr(const int* src, const int* dst, int ndst,
                      int* rowptr, int* col, int* deg, int* parts) {
    int n1 = ndst + 1;
    zero_kernel<<<(n1 + 255) / 256, 256>>>(deg, n1);
    hist_kernel<<<2048, 256>>>(dst, deg, NEDGE);
    int nb = (n1 + 1023) / 1024;
    scan_blocks<<<nb, 256>>>(deg, rowptr, parts, n1);
    scan_partials<<<1, 256>>>(parts, nb);
    scan_add<<<nb, 256>>>(rowptr, parts, n1);
    zero_kernel<<<(n1 + 255) / 256, 256>>>(deg, n1);
    fill_kernel<<<2048, 256>>>(src, dst, rowptr, deg, col, NEDGE);
}

extern "C" void kernel_launch(void* const* d_in, const int* in_sizes, int n_in,
                              void* d_out, int out_size) {
    (void)in_sizes; (void)n_in; (void)out_size;
    const float* x_host  = (const float*)d_in[0];
    const float* x_flow  = (const float*)d_in[1];
    const int*   ehf_src = (const int*)d_in[2];
    const int*   ehf_dst = (const int*)d_in[3];
    const int*   efh_src = (const int*)d_in[4];
    const int*   efh_dst = (const int*)d_in[5];
    const float* Wl      = (const float*)d_in[6];  // [2,2,128,128]
    const float* bl      = (const float*)d_in[7];  // [2,2,128]
    const float* Wr      = (const float*)d_in[8];
    const float* br      = (const float*)d_in[9];
    const float* W_out   = (const float*)d_in[10]; // [128,32]
    const float* b_out   = (const float*)d_in[11]; // [32]
    float* out = (float*)d_out;

    int *deg, *rpf, *rph, *colf, *colh, *parts;
    float *mean, *fa, *fb, *ha, *hb;
    cudaGetSymbolAddress((void**)&deg,   g_deg);
    cudaGetSymbolAddress((void**)&rpf,   g_rowptr_f);
    cudaGetSymbolAddress((void**)&rph,   g_rowptr_h);
    cudaGetSymbolAddress((void**)&colf,  g_col_f);
    cudaGetSymbolAddress((void**)&colh,  g_col_h);
    cudaGetSymbolAddress((void**)&parts, g_partials);
    cudaGetSymbolAddress((void**)&mean,  g_mean);
    cudaGetSymbolAddress((void**)&fa,    g_fa);
    cudaGetSymbolAddress((void**)&fb,    g_fb);
    cudaGetSymbolAddress((void**)&ha,    g_ha);
    cudaGetSymbolAddress((void**)&hb,    g_hb);

    // CSR for both directions (edges constant per call -> deterministic sets)
    build_csr(ehf_src, ehf_dst, N_FLOWN, rpf, colf, deg, parts);
    build_csr(efh_src, efh_dst, N_HOSTN, rph, colh, deg, parts);

    const float* fcur = x_flow;
    const float* hcur = x_host;
    float* fnext[2] = {fa, fb};
    float* hnext[2] = {ha, hb};

    for (int l = 0; l < 2; l++) {
        const float* wl0 = Wl + (size_t)(l * 2 + 0) * DIM * DIM;
        const float* wr0 = Wr + (size_t)(l * 2 + 0) * DIM * DIM;
        const float* bl0 = bl + (size_t)(l * 2 + 0) * DIM;
        const float* br0 = br + (size_t)(l * 2 + 0) * DIM;
        const float* wl1 = Wl + (size_t)(l * 2 + 1) * DIM * DIM;
        const float* wr1 = Wr + (size_t)(l * 2 + 1) * DIM * DIM;
        const float* bl1 = bl + (size_t)(l * 2 + 1) * DIM;
        const float* br1 = br + (size_t)(l * 2 + 1) * DIM;

        // flow update: mean over host neighbors
        aggregate_kernel<<<(N_FLOWN + 7) / 8, 256>>>(hcur, rpf, colf, mean, N_FLOWN);
        gemm_kernel<64, 128, 32, true, true><<<(N_FLOWN + 63) / 64, 256>>>(
            mean, fcur, wl0, wr0, bl0, br0, fnext[l], N_FLOWN);

        // host update: mean over flow neighbors (uses pre-layer fcur)
        aggregate_kernel<<<(N_HOSTN + 7) / 8, 256>>>(fcur, rph, colh, mean, N_HOSTN);
        gemm_kernel<64, 128, 32, true, true><<<(N_HOSTN + 63) / 64, 256>>>(
            mean, hcur, wl1, wr1, bl1, br1, hnext[l], N_HOSTN);

        fcur = fnext[l];
        hcur = hnext[l];
    }

    // final projection: out = f @ W_out + b_out
    gemm_kernel<64, 32, 32, false, false><<<(N_FLOWN + 63) / 64, 256>>>(
        fcur, nullptr, W_out, nullptr, b_out, nullptr, out, N_FLOWN);
}

// round 3
// speedup vs baseline: 1.6975x; 1.6975x over previous
#include <cuda_runtime.h>
#include <cuda_bf16.h>
#include <cstdint>

#define N_HOSTN 50000
#define N_FLOWN 200000
#define NEDGE   1000000
#define DIM     128
#define D_OUT   32

// ---------------- device scratch (static: no allocations allowed) ----------
__device__ int   g_deg[N_FLOWN + 1];
__device__ int   g_rowptr_f[N_FLOWN + 1];
__device__ int   g_rowptr_h[N_HOSTN + 1];
__device__ int   g_col_f[NEDGE];
__device__ int   g_col_h[NEDGE];
__device__ int   g_partials[256];
__device__ float g_mean[(size_t)N_FLOWN * DIM];
__device__ float g_fa[(size_t)N_FLOWN * DIM];
__device__ float g_fb[(size_t)N_FLOWN * DIM];
__device__ float g_ha[(size_t)N_HOSTN * DIM];
__device__ float g_hb[(size_t)N_HOSTN * DIM];
// transposed weights, bf16 hi/lo: 4 dual-GEMMs [128 n][256 k] + final [32 n][128 k]
__device__ __nv_bfloat16 g_bhi[4 * 128 * 256];
__device__ __nv_bfloat16 g_blo[4 * 128 * 256];
__device__ __nv_bfloat16 g_fhi[32 * 128];
__device__ __nv_bfloat16 g_flo[32 * 128];

// ---------------- helpers ----------------------------------------------------
__device__ __forceinline__ uint32_t smem_u32(const void* p) {
    return (uint32_t)__cvta_generic_to_shared(p);
}

__device__ __forceinline__ void ldsm4(uint32_t* r, uint32_t addr) {
    asm volatile("ldmatrix.sync.aligned.m8n8.x4.shared.b16 {%0,%1,%2,%3}, [%4];"
                 : "=r"(r[0]), "=r"(r[1]), "=r"(r[2]), "=r"(r[3]) : "r"(addr));
}

__device__ __forceinline__ void mma_bf16(float* c, const uint32_t* a, const uint32_t* b) {
    asm volatile(
        "mma.sync.aligned.m16n8k16.row.col.f32.bf16.bf16.f32 "
        "{%0,%1,%2,%3}, {%4,%5,%6,%7}, {%8,%9}, {%0,%1,%2,%3};"
        : "+f"(c[0]), "+f"(c[1]), "+f"(c[2]), "+f"(c[3])
        : "r"(a[0]), "r"(a[1]), "r"(a[2]), "r"(a[3]), "r"(b[0]), "r"(b[1]));
}

__device__ __forceinline__ uint32_t pack2(__nv_bfloat16 a, __nv_bfloat16 b) {
    uint32_t lo = (uint32_t)__bfloat16_as_ushort(a);
    uint32_t hi = (uint32_t)__bfloat16_as_ushort(b);
    return lo | (hi << 16);
}

// ---------------- small utility kernels ------------------------------------
__global__ void zero_kernel(int* p, int n) {
    int i = blockIdx.x * blockDim.x + threadIdx.x;
    if (i < n) p[i] = 0;
}

__global__ void hist_kernel(const int* __restrict__ dst, int* __restrict__ deg, int n) {
    for (int i = blockIdx.x * blockDim.x + threadIdx.x; i < n; i += gridDim.x * blockDim.x)
        atomicAdd(&deg[dst[i]], 1);
}

__global__ void scan_blocks(const int* __restrict__ in, int* __restrict__ out,
                            int* __restrict__ partials, int n) {
    __shared__ int sh[256];
    int t = threadIdx.x;
    int base = blockIdx.x * 1024 + t * 4;
    int v0 = (base + 0 < n) ? in[base + 0] : 0;
    int v1 = (base + 1 < n) ? in[base + 1] : 0;
    int v2 = (base + 2 < n) ? in[base + 2] : 0;
    int v3 = (base + 3 < n) ? in[base + 3] : 0;
    int s = v0 + v1 + v2 + v3;
    sh[t] = s;
    __syncthreads();
    for (int off = 1; off < 256; off <<= 1) {
        int y = (t >= off) ? sh[t - off] : 0;
        __syncthreads();
        sh[t] += y;
        __syncthreads();
    }
    int excl = sh[t] - s;
    if (t == 255) partials[blockIdx.x] = sh[255];
    int run = excl;
    if (base + 0 < n) out[base + 0] = run; run += v0;
    if (base + 1 < n) out[base + 1] = run; run += v1;
    if (base + 2 < n) out[base + 2] = run; run += v2;
    if (base + 3 < n) out[base + 3] = run;
}

__global__ void scan_partials(int* partials, int nb) {
    __shared__ int sh[256];
    int t = threadIdx.x;
    int v = (t < nb) ? partials[t] : 0;
    sh[t] = v;
    __syncthreads();
    for (int off = 1; off < 256; off <<= 1) {
        int y = (t >= off) ? sh[t - off] : 0;
        __syncthreads();
        sh[t] += y;
        __syncthreads();
    }
    if (t < nb) partials[t] = sh[t] - v;
}

__global__ void scan_add(int* __restrict__ out, const int* __restrict__ partials, int n) {
    for (int i = blockIdx.x * blockDim.x + threadIdx.x; i < n; i += gridDim.x * blockDim.x)
        out[i] += partials[i >> 10];
}

__global__ void fill_kernel(const int* __restrict__ src, const int* __restrict__ dst,
                            const int* __restrict__ rowptr, int* __restrict__ cursor,
                            int* __restrict__ col, int n) {
    for (int e = blockIdx.x * blockDim.x + threadIdx.x; e < n; e += gridDim.x * blockDim.x) {
        int d = dst[e];
        int p = rowptr[d] + atomicAdd(&cursor[d], 1);
        col[p] = src[e];
    }
}

// precompute transposed bf16 hi/lo weight planes ([n][k] layout)
__global__ void prep_weights(const float* __restrict__ Wl, const float* __restrict__ Wr,
                             const float* __restrict__ W_out,
                             __nv_bfloat16* __restrict__ bhi, __nv_bfloat16* __restrict__ blo,
                             __nv_bfloat16* __restrict__ fhi, __nv_bfloat16* __restrict__ flo) {
    int i = blockIdx.x * blockDim.x + threadIdx.x;
    const int ndual = 4 * 128 * 256;
    if (i < ndual) {
        int g = i / (128 * 256);
        int r = i % (128 * 256);
        int n = r / 256;
        int k = r % 256;
        float v;
        if (k < DIM) v = Wl[(size_t)g * DIM * DIM + (size_t)k * DIM + n];
        else         v = Wr[(size_t)g * DIM * DIM + (size_t)(k - DIM) * DIM + n];
        __nv_bfloat16 h = __float2bfloat16(v);
        bhi[i] = h;
        blo[i] = __float2bfloat16(v - __bfloat162float(h));
    } else if (i < ndual + 32 * 128) {
        int r = i - ndual;
        int n = r / 128;
        int k = r % 128;
        float v = W_out[(size_t)k * D_OUT + n];
        __nv_bfloat16 h = __float2bfloat16(v);
        fhi[r] = h;
        flo[r] = __float2bfloat16(v - __bfloat162float(h));
    }
}

// ---------------- mean aggregation (pull via CSR) ---------------------------
__global__ void aggregate_kernel(const float* __restrict__ xsrc,
                                 const int* __restrict__ rowptr,
                                 const int* __restrict__ col,
                                 float* __restrict__ outmean, int ndst) {
    int warp = (blockIdx.x * blockDim.x + threadIdx.x) >> 5;
    int lane = threadIdx.x & 31;
    if (warp >= ndst) return;
    int start = rowptr[warp];
    int end   = rowptr[warp + 1];
    const float4* base = (const float4*)xsrc;
    float4 acc = make_float4(0.f, 0.f, 0.f, 0.f);
#pragma unroll 2
    for (int e = start; e < end; e++) {
        int s = __ldg(&col[e]);
        float4 v = __ldg(&base[(size_t)s * 32 + lane]);
        acc.x += v.x; acc.y += v.y; acc.z += v.z; acc.w += v.w;
    }
    int deg = end - start;
    float inv = 1.f / (float)(deg > 1 ? deg : 1);
    acc.x *= inv; acc.y *= inv; acc.z *= inv; acc.w *= inv;
    ((float4*)outmean)[(size_t)warp * 32 + lane] = acc;
}

// ---------------- mma.sync bf16 GEMM, 3-pass hi/lo split ---------------------
// C[M,BN] = act( [A0|A1][M,KTOT] @ B[KTOT,BN] + bias0 + bias1 )
// B pre-transposed K-major hi/lo planes: Bhi[n*KTOT + k].
// CTA tile 128 x BN ; 8 warps = WROWS x (8/WROWS) grid of 16*TM x 8*TN warp tiles.
template <int BN, int WROWS, int KTOT, bool DUAL, bool ACT>
__global__ __launch_bounds__(256) void mma_gemm(
    const float* __restrict__ A0, const float* __restrict__ A1,
    const __nv_bfloat16* __restrict__ Bhi, const __nv_bfloat16* __restrict__ Blo,
    const float* __restrict__ bias0, const float* __restrict__ bias1,
    float* __restrict__ C, int M)
{
    constexpr int WCOLS  = 8 / WROWS;
    constexpr int WARP_M = 128 / WROWS;
    constexpr int WARP_N = BN / WCOLS;
    constexpr int TM = WARP_M / 16;
    constexpr int TN = WARP_N / 8;
    constexpr int AS = 40;  // padded smem row stride (elems) -> conflict-free ldmatrix

    __shared__ __align__(16) __nv_bfloat16 sA[2][128 * AS];
    __shared__ __align__(16) __nv_bfloat16 sB[2][BN * AS];
    __shared__ float s_bias[BN];

    const int tid  = threadIdx.x;
    const int wid  = tid >> 5;
    const int lane = tid & 31;
    const int wrow = wid / WCOLS;
    const int wcol = wid % WCOLS;
    const int rowbase = blockIdx.x * 128;

    if (tid < BN) s_bias[tid] = bias0[tid] + (DUAL ? bias1[tid] : 0.f);

    float acc[TM][TN][4];
#pragma unroll
    for (int i = 0; i < TM; i++)
#pragma unroll
        for (int j = 0; j < TN; j++)
#pragma unroll
            for (int q = 0; q < 4; q++) acc[i][j][q] = 0.f;

    // precomputed ldmatrix byte offsets (same smem tile positions every k-iter)
    const uint32_t uA0 = smem_u32(sA[0]);
    const uint32_t uA1 = smem_u32(sA[1]);
    const uint32_t uB0 = smem_u32(sB[0]);
    const uint32_t uB1 = smem_u32(sB[1]);
    uint32_t aoff[TM][2];
#pragma unroll
    for (int i = 0; i < TM; i++)
#pragma unroll
        for (int ks = 0; ks < 2; ks++) {
            int row = wrow * WARP_M + i * 16 + (lane & 15);
            int colk = ks * 16 + (lane >> 4) * 8;
            aoff[i][ks] = (uint32_t)(row * AS + colk) * 2;
        }
    uint32_t boff[TN / 2][2];
#pragma unroll
    for (int jj = 0; jj < TN / 2; jj++)
#pragma unroll
        for (int ks = 0; ks < 2; ks++) {
            int n = wcol * WARP_N + jj * 16 + (lane & 7) + ((lane >> 4) & 1) * 8;
            int k = ks * 16 + ((lane >> 3) & 1) * 8;
            boff[jj][ks] = (uint32_t)(n * AS + k) * 2;
        }

    for (int k0 = 0; k0 < KTOT; k0 += 32) {
        const float* A = (DUAL && k0 >= DIM) ? A1 : A0;
        const int ka = DUAL ? (k0 & (DIM - 1)) : k0;

        // A: 128 rows x 32 fp32 -> bf16 hi/lo into padded smem
#pragma unroll
        for (int p = 0; p < 4; p++) {
            int idx = p * 256 + tid;
            int r = idx >> 3;
            int q = idx & 7;
            int row = rowbase + r;
            float4 v = make_float4(0.f, 0.f, 0.f, 0.f);
            if (row < M) v = *(const float4*)(A + (size_t)row * DIM + ka + q * 4);
            __nv_bfloat16 h0 = __float2bfloat16(v.x);
            __nv_bfloat16 h1 = __float2bfloat16(v.y);
            __nv_bfloat16 h2 = __float2bfloat16(v.z);
            __nv_bfloat16 h3 = __float2bfloat16(v.w);
            __nv_bfloat16 l0 = __float2bfloat16(v.x - __bfloat162float(h0));
            __nv_bfloat16 l1 = __float2bfloat16(v.y - __bfloat162float(h1));
            __nv_bfloat16 l2 = __float2bfloat16(v.z - __bfloat162float(h2));
            __nv_bfloat16 l3 = __float2bfloat16(v.w - __bfloat162float(h3));
            int o = r * AS + q * 4;
            *(uint2*)&sA[0][o] = make_uint2(pack2(h0, h1), pack2(h2, h3));
            *(uint2*)&sA[1][o] = make_uint2(pack2(l0, l1), pack2(l2, l3));
        }
        // B: BN rows(n) x 32 k bf16 per plane
#pragma unroll
        for (int p = 0; p < BN / 32; p++) {
            int idx = p * 256 + tid;
            int plane = idx / (BN * 4);
            int rem = idx % (BN * 4);
            int r = rem >> 2;
            int q = rem & 3;
            const __nv_bfloat16* src = (plane ? Blo : Bhi) + (size_t)r * KTOT + k0 + q * 8;
            *(uint4*)&sB[plane][r * AS + q * 8] = *(const uint4*)src;
        }
        __syncthreads();

#pragma unroll
        for (int ks = 0; ks < 2; ks++) {
            uint32_t ah[TM][4], al[TM][4];
#pragma unroll
            for (int i = 0; i < TM; i++) {
                ldsm4(ah[i], uA0 + aoff[i][ks]);
                ldsm4(al[i], uA1 + aoff[i][ks]);
            }
            uint32_t bh[TN][2], blo_[TN][2];
#pragma unroll
            for (int jj = 0; jj < TN / 2; jj++) {
                uint32_t r4[4];
                ldsm4(r4, uB0 + boff[jj][ks]);
                bh[2 * jj][0] = r4[0]; bh[2 * jj][1] = r4[1];
                bh[2 * jj + 1][0] = r4[2]; bh[2 * jj + 1][1] = r4[3];
                ldsm4(r4, uB1 + boff[jj][ks]);
                blo_[2 * jj][0] = r4[0]; blo_[2 * jj][1] = r4[1];
                blo_[2 * jj + 1][0] = r4[2]; blo_[2 * jj + 1][1] = r4[3];
            }
#pragma unroll
            for (int i = 0; i < TM; i++)
#pragma unroll
                for (int j = 0; j < TN; j++) {
                    mma_bf16(acc[i][j], ah[i], bh[j]);
                    mma_bf16(acc[i][j], ah[i], blo_[j]);
                    mma_bf16(acc[i][j], al[i], bh[j]);
                }
        }
        __syncthreads();
    }

    // epilogue: bias (+leaky relu), fp32 store
#pragma unroll
    for (int i = 0; i < TM; i++) {
#pragma unroll
        for (int j = 0; j < TN; j++) {
            int row0 = rowbase + wrow * WARP_M + i * 16 + (lane >> 2);
            int colb = wcol * WARP_N + j * 8 + (lane & 3) * 2;
            float b0 = s_bias[colb], b1 = s_bias[colb + 1];
#pragma unroll
            for (int h = 0; h < 2; h++) {
                int row = row0 + h * 8;
                if (row < M) {
                    float vx = acc[i][j][2 * h + 0] + b0;
                    float vy = acc[i][j][2 * h + 1] + b1;
                    if (ACT) {
                        vx = vx > 0.f ? vx : 0.01f * vx;
                        vy = vy > 0.f ? vy : 0.01f * vy;
                    }
                    *(float2*)&C[(size_t)row * BN + colb] = make_float2(vx, vy);
                }
            }
        }
    }
}

// ---------------- host side -------------------------------------------------
static void build_csr(const int* src, const int* dst, int ndst,
                      int* rowptr, int* col, int* deg, int* parts) {
    int n1 = ndst + 1;
    zero_kernel<<<(n1 + 255) / 256, 256>>>(deg, n1);
    hist_kernel<<<2048, 256>>>(dst, deg, NEDGE);
    int nb = (n1 + 1023) / 1024;
    scan_blocks<<<nb, 256>>>(deg, rowptr, parts, n1);
    scan_partials<<<1, 256>>>(parts, nb);
    scan_add<<<nb, 256>>>(rowptr, parts, n1);
    zero_kernel<<<(n1 + 255) / 256, 256>>>(deg, n1);
    fill_kernel<<<2048, 256>>>(src, dst, rowptr, deg, col, NEDGE);
}

extern "C" void kernel_launch(void* const* d_in, const int* in_sizes, int n_in,
                              void* d_out, int out_size) {
    (void)in_sizes; (void)n_in; (void)out_size;
    const float* x_host  = (const float*)d_in[0];
    const float* x_flow  = (const float*)d_in[1];
    const int*   ehf_src = (const int*)d_in[2];
    const int*   ehf_dst = (const int*)d_in[3];
    const int*   efh_src = (const int*)d_in[4];
    const int*   efh_dst = (const int*)d_in[5];
    const float* Wl      = (const float*)d_in[6];
    const float* bl      = (const float*)d_in[7];
    const float* Wr      = (const float*)d_in[8];
    const float* br      = (const float*)d_in[9];
    const float* W_out   = (const float*)d_in[10];
    const float* b_out   = (const float*)d_in[11];
    float* out = (float*)d_out;

    int *deg, *rpf, *rph, *colf, *colh, *parts;
    float *mean, *fa, *fb, *ha, *hb;
    __nv_bfloat16 *bhi, *blo, *fhi, *flo;
    cudaGetSymbolAddress((void**)&deg,   g_deg);
    cudaGetSymbolAddress((void**)&rpf,   g_rowptr_f);
    cudaGetSymbolAddress((void**)&rph,   g_rowptr_h);
    cudaGetSymbolAddress((void**)&colf,  g_col_f);
    cudaGetSymbolAddress((void**)&colh,  g_col_h);
    cudaGetSymbolAddress((void**)&parts, g_partials);
    cudaGetSymbolAddress((void**)&mean,  g_mean);
    cudaGetSymbolAddress((void**)&fa,    g_fa);
    cudaGetSymbolAddress((void**)&fb,    g_fb);
    cudaGetSymbolAddress((void**)&ha,    g_ha);
    cudaGetSymbolAddress((void**)&hb,    g_hb);
    cudaGetSymbolAddress((void**)&bhi,   g_bhi);
    cudaGetSymbolAddress((void**)&blo,   g_blo);
    cudaGetSymbolAddress((void**)&fhi,   g_fhi);
    cudaGetSymbolAddress((void**)&flo,   g_flo);

    // weights -> transposed bf16 hi/lo planes
    prep_weights<<<(4 * 128 * 256 + 32 * 128 + 255) / 256, 256>>>(
        Wl, Wr, W_out, bhi, blo, fhi, flo);

    // CSR for both directions
    build_csr(ehf_src, ehf_dst, N_FLOWN, rpf, colf, deg, parts);
    build_csr(efh_src, efh_dst, N_HOSTN, rph, colh, deg, parts);

    const float* fcur = x_flow;
    const float* hcur = x_host;
    float* fnext[2] = {fa, fb};
    float* hnext[2] = {ha, hb};

    for (int l = 0; l < 2; l++) {
        int g0 = l * 2 + 0;
        int g1 = l * 2 + 1;
        const float* bl0 = bl + (size_t)g0 * DIM;
        const float* br0 = br + (size_t)g0 * DIM;
        const float* bl1 = bl + (size_t)g1 * DIM;
        const float* br1 = br + (size_t)g1 * DIM;

        // flow update: mean over host neighbors, then [mean|f] @ [Wl;Wr]
        aggregate_kernel<<<(N_FLOWN + 7) / 8, 256>>>(hcur, rpf, colf, mean, N_FLOWN);
        mma_gemm<128, 2, 256, true, true><<<(N_FLOWN + 127) / 128, 256>>>(
            mean, fcur, bhi + (size_t)g0 * 128 * 256, blo + (size_t)g0 * 128 * 256,
            bl0, br0, fnext[l], N_FLOWN);

        // host update: mean over flow neighbors (pre-layer fcur)
        aggregate_kernel<<<(N_HOSTN + 7) / 8, 256>>>(fcur, rph, colh, mean, N_HOSTN);
        mma_gemm<128, 2, 256, true, true><<<(N_HOSTN + 127) / 128, 256>>>(
            mean, hcur, bhi + (size_t)g1 * 128 * 256, blo + (size_t)g1 * 128 * 256,
            bl1, br1, hnext[l], N_HOSTN);

        fcur = fnext[l];
        hcur = hnext[l];
    }

    // final projection: out = f @ W_out + b_out
    mma_gemm<32, 8, 128, false, false><<<(N_FLOWN + 127) / 128, 256>>>(
        fcur, nullptr, fhi, flo, b_out, nullptr, out, N_FLOWN);
}